// round 1
// baseline (speedup 1.0000x reference)
#include <cuda_runtime.h>
#include <math.h>

#define NPART 16
#define DDIM 3
#define HID 64
#define DLAT 5
#define TEMB 16
#define NFREQ 8
#define NPAIR 120
#define RHOIN 28
#define NTHREADS 128
#define BPB 4

__device__ __forceinline__ float gelu_f(float x) {
    return 0.5f * x * (1.0f + erff(x * 0.70710678118654752f));
}

// Deterministic block-wide sum over 128 threads (4 warps).
__device__ __forceinline__ float blockReduceSum(float v, float* sRed) {
    const int tid = threadIdx.x;
    #pragma unroll
    for (int o = 16; o > 0; o >>= 1)
        v += __shfl_down_sync(0xffffffffu, v, o);
    if ((tid & 31) == 0) sRed[tid >> 5] = v;
    __syncthreads();
    float r = sRed[0] + sRed[1] + sRed[2] + sRed[3];
    __syncthreads();
    return r;
}

__global__ __launch_bounds__(NTHREADS, 4)
void tau_jastrow_kernel(
    const float* __restrict__ x, const float* __restrict__ tau, const float* __restrict__ freqs,
    const float* __restrict__ phi_w0, const float* __restrict__ phi_b0,
    const float* __restrict__ phi_w1, const float* __restrict__ phi_b1,
    const float* __restrict__ phi_w2, const float* __restrict__ phi_b2,
    const float* __restrict__ psi_w0, const float* __restrict__ psi_b0,
    const float* __restrict__ psi_w1, const float* __restrict__ psi_b1,
    const float* __restrict__ psi_w2, const float* __restrict__ psi_b2,
    const float* __restrict__ rho_w0, const float* __restrict__ rho_b0,
    const float* __restrict__ rho_w1, const float* __restrict__ rho_b1,
    const float* __restrict__ rho_w2, const float* __restrict__ rho_b2,
    const float* __restrict__ tp_w0, const float* __restrict__ tp_b0,
    const float* __restrict__ tp_w1, const float* __restrict__ tp_b1,
    float* __restrict__ out, int Btot)
{
    __shared__ __align__(16) float sPsiW1[HID * HID];
    __shared__ __align__(16) float sPhiW1[HID * HID];
    __shared__ __align__(16) float sPsiW0[6 * HID];
    __shared__ __align__(16) float sPhiW0[DDIM * HID];
    __shared__ __align__(16) float sPsiW2[HID * DLAT];
    __shared__ __align__(16) float sPhiW2[HID * DLAT];
    __shared__ float sPsiB0[HID], sPsiB1[HID], sPsiB2[DLAT + 3];
    __shared__ float sPhiB0[HID], sPhiB1[HID], sPhiB2[DLAT + 3];
    __shared__ float sX[NPART * DDIM];
    __shared__ float sH0[NPART * 68];     // phi hidden, padded stride 68
    __shared__ float sRed[4];
    __shared__ float sRhoIn[RHOIN];
    __shared__ float sRH0[HID];
    __shared__ float sTF[2 * NFREQ + 1];
    __shared__ float sHT[TEMB];

    const int tid = threadIdx.x;

    // ---- cooperative weight load into smem (once per block) ----
    for (int i = tid; i < HID * HID; i += NTHREADS) { sPsiW1[i] = psi_w1[i]; sPhiW1[i] = phi_w1[i]; }
    for (int i = tid; i < 6 * HID; i += NTHREADS) sPsiW0[i] = psi_w0[i];
    for (int i = tid; i < DDIM * HID; i += NTHREADS) sPhiW0[i] = phi_w0[i];
    for (int i = tid; i < HID * DLAT; i += NTHREADS) { sPsiW2[i] = psi_w2[i]; sPhiW2[i] = phi_w2[i]; }
    if (tid < HID) { sPsiB0[tid] = psi_b0[tid]; sPsiB1[tid] = psi_b1[tid];
                     sPhiB0[tid] = phi_b0[tid]; sPhiB1[tid] = phi_b1[tid]; }
    if (tid < DLAT) { sPsiB2[tid] = psi_b2[tid]; sPhiB2[tid] = phi_b2[tid]; }

    // ---- pair indices (triu k=1 row-major order) ----
    int pi = 0, pj = 0;
    {
        int p2 = tid, i2 = 0, cnt = NPART - 1;
        while (cnt > 0 && p2 >= cnt) { p2 -= cnt; i2++; cnt--; }
        pi = i2; pj = i2 + 1 + p2;
        if (pj >= NPART) pj = NPART - 1;
    }
    const bool active = (tid < NPAIR);
    const float gamma = ((pi < NPART / 2) == (pj < NPART / 2))
                        ? (1.0f / (DDIM + 1)) : (1.0f / (DDIM - 1));

    const int base = blockIdx.x * BPB;
    for (int b = base; b < base + BPB && b < Btot; ++b) {
        if (tid < NPART * DDIM) sX[tid] = x[(size_t)b * (NPART * DDIM) + tid];
        __syncthreads();  // also orders the weight loads on first iteration

        // ---- pair features ----
        float feat[6] = {0.f, 0.f, 0.f, 0.f, 0.f, 0.f};
        float gate = 0.f, s1v = 0.f, cuspv = 0.f;
        if (active) {
            float d0 = sX[pi * 3 + 0] - sX[pj * 3 + 0];
            float d1 = sX[pi * 3 + 1] - sX[pj * 3 + 1];
            float d2 = sX[pi * 3 + 2] - sX[pj * 3 + 2];
            float r2 = d0 * d0 + d1 * d1 + d2 * d2;
            float r = sqrtf(r2 + 1.1920929e-7f);
            float rt2 = r2 + 0.04f;            // eps^2 = (0.2)^2, a_ho = 1
            float u = rt2 * 25.0f;
            s1v = log1pf(u);
            feat[0] = s1v;
            feat[1] = r2 / rt2;
            feat[2] = u * expf(-u);
            feat[3] = expf(-0.25f * s1v);
            feat[4] = expf(-s1v);
            feat[5] = expf(-4.0f * s1v);
            gate = r2 / (r2 + 0.09f);          // rg^2 = 0.09
            cuspv = gamma * r * expf(-r);
        }

        // ---- psi MLP: one pair per thread, h0 streamed into 64 reg accumulators ----
        float h1[HID];
        #pragma unroll
        for (int q = 0; q < HID; q++) h1[q] = sPsiB1[q];
        #pragma unroll 2
        for (int k = 0; k < HID; k++) {
            float a = sPsiB0[k];
            #pragma unroll
            for (int i2 = 0; i2 < 6; i2++) a += feat[i2] * sPsiW0[i2 * HID + k];
            float h0k = gelu_f(a);
            const float4* w = reinterpret_cast<const float4*>(&sPsiW1[k * HID]);
            #pragma unroll
            for (int q = 0; q < 16; q++) {
                float4 wv = w[q];
                h1[4 * q + 0] += h0k * wv.x;
                h1[4 * q + 1] += h0k * wv.y;
                h1[4 * q + 2] += h0k * wv.z;
                h1[4 * q + 3] += h0k * wv.w;
            }
        }
        float pout[DLAT];
        #pragma unroll
        for (int d = 0; d < DLAT; d++) pout[d] = sPsiB2[d];   // b2 BEFORE gate
        #pragma unroll 8
        for (int q = 0; q < HID; q++) {
            float g = gelu_f(h1[q]);
            #pragma unroll
            for (int d = 0; d < DLAT; d++) pout[d] += g * sPsiW2[q * DLAT + d];
        }

        float gs1 = blockReduceSum(s1v, sRed);
        float gcusp = blockReduceSum(cuspv, sRed);
        float gpsi[DLAT];
        #pragma unroll
        for (int d = 0; d < DLAT; d++) gpsi[d] = blockReduceSum(pout[d] * gate, sRed);
        if (tid == 0) {
            sRhoIn[11] = gs1 * (1.0f / NPAIR);
            #pragma unroll
            for (int d = 0; d < DLAT; d++) sRhoIn[5 + d] = gpsi[d] * (1.0f / NPAIR);
        }

        // ---- phi h0: 16 rows x 8 k-chunks across 128 threads ----
        {
            int r0 = tid >> 3;
            int kb = (tid & 7) * 8;
            float xv0 = sX[r0 * 3 + 0], xv1 = sX[r0 * 3 + 1], xv2 = sX[r0 * 3 + 2];
            #pragma unroll
            for (int kk = 0; kk < 8; kk++) {
                int k = kb + kk;
                float a = sPhiB0[k] + xv0 * sPhiW0[0 * HID + k]
                                    + xv1 * sPhiW0[1 * HID + k]
                                    + xv2 * sPhiW0[2 * HID + k];
                sH0[r0 * 68 + k] = gelu_f(a);
            }
        }
        __syncthreads();
        // ---- phi h1 + out: 16 rows x 8 j-chunks ----
        {
            int r0 = tid >> 3;
            int jb = (tid & 7) * 8;
            float acc[8];
            #pragma unroll
            for (int q = 0; q < 8; q++) acc[q] = sPhiB1[jb + q];
            #pragma unroll 4
            for (int k = 0; k < HID; k++) {
                float h0v = sH0[r0 * 68 + k];
                const float4* w = reinterpret_cast<const float4*>(&sPhiW1[k * HID + jb]);
                float4 w0 = w[0], w1 = w[1];
                acc[0] += h0v * w0.x; acc[1] += h0v * w0.y;
                acc[2] += h0v * w0.z; acc[3] += h0v * w0.w;
                acc[4] += h0v * w1.x; acc[5] += h0v * w1.y;
                acc[6] += h0v * w1.z; acc[7] += h0v * w1.w;
            }
            float pp[DLAT] = {0.f, 0.f, 0.f, 0.f, 0.f};
            #pragma unroll
            for (int q = 0; q < 8; q++) {
                float g = gelu_f(acc[q]);
                #pragma unroll
                for (int d = 0; d < DLAT; d++) pp[d] += g * sPhiW2[(jb + q) * DLAT + d];
            }
            #pragma unroll
            for (int d = 0; d < DLAT; d++) {
                float s = blockReduceSum(pp[d], sRed);
                if (tid == 0) sRhoIn[d] = s * (1.0f / NPART) + sPhiB2[d];
            }
        }
        // ---- r2_mean ----
        {
            float v = (tid < NPART * DDIM) ? sX[tid] * sX[tid] : 0.f;
            float s = blockReduceSum(v, sRed);
            if (tid == 0) sRhoIn[10] = s * (1.0f / (NPART * DDIM));
        }
        // ---- temb ----
        float tb = tau[b];
        if (tid == 0) sTF[0] = tb;
        if (tid < NFREQ) {
            float ft = freqs[tid] * tb;
            sTF[1 + tid] = sinf(ft);
            sTF[1 + NFREQ + tid] = cosf(ft);
        }
        __syncthreads();
        if (tid < TEMB) {
            float a = tp_b0[tid];
            #pragma unroll
            for (int i2 = 0; i2 < 2 * NFREQ + 1; i2++) a += sTF[i2] * tp_w0[i2 * TEMB + tid];
            sHT[tid] = gelu_f(a);
        }
        __syncthreads();
        if (tid < TEMB) {
            float a = tp_b1[tid];
            #pragma unroll
            for (int i2 = 0; i2 < TEMB; i2++) a += sHT[i2] * tp_w1[i2 * TEMB + tid];
            sRhoIn[12 + tid] = a;   // no gelu on second temb layer
        }
        __syncthreads();
        // ---- rho MLP (28 -> 64 -> 64 -> 1), weights uniform from L1 ----
        if (tid < HID) {
            float a = rho_b0[tid];
            #pragma unroll 4
            for (int i2 = 0; i2 < RHOIN; i2++) a += sRhoIn[i2] * rho_w0[i2 * HID + tid];
            sRH0[tid] = gelu_f(a);
        }
        __syncthreads();
        float part = 0.f;
        if (tid < HID) {
            float a = rho_b1[tid];
            #pragma unroll 4
            for (int k = 0; k < HID; k++) a += sRH0[k] * rho_w1[k * HID + tid];
            part = gelu_f(a) * rho_w2[tid];
        }
        float osum = blockReduceSum(part, sRed);
        if (tid == 0) out[b] = osum + rho_b2[0] + gcusp;
        __syncthreads();
    }
}

extern "C" void kernel_launch(void* const* d_in, const int* in_sizes, int n_in,
                              void* d_out, int out_size) {
    const float* x      = (const float*)d_in[0];
    const float* tau    = (const float*)d_in[1];
    const float* freqs  = (const float*)d_in[2];
    const float* phi_w0 = (const float*)d_in[3];
    const float* phi_b0 = (const float*)d_in[4];
    const float* phi_w1 = (const float*)d_in[5];
    const float* phi_b1 = (const float*)d_in[6];
    const float* phi_w2 = (const float*)d_in[7];
    const float* phi_b2 = (const float*)d_in[8];
    const float* psi_w0 = (const float*)d_in[9];
    const float* psi_b0 = (const float*)d_in[10];
    const float* psi_w1 = (const float*)d_in[11];
    const float* psi_b1 = (const float*)d_in[12];
    const float* psi_w2 = (const float*)d_in[13];
    const float* psi_b2 = (const float*)d_in[14];
    const float* rho_w0 = (const float*)d_in[15];
    const float* rho_b0 = (const float*)d_in[16];
    const float* rho_w1 = (const float*)d_in[17];
    const float* rho_b1 = (const float*)d_in[18];
    const float* rho_w2 = (const float*)d_in[19];
    const float* rho_b2 = (const float*)d_in[20];
    const float* tp_w0  = (const float*)d_in[21];
    const float* tp_b0  = (const float*)d_in[22];
    const float* tp_w1  = (const float*)d_in[23];
    const float* tp_b1  = (const float*)d_in[24];
    float* out = (float*)d_out;

    const int Btot = in_sizes[1];               // tau has B elements
    const int nblocks = (Btot + BPB - 1) / BPB;
    tau_jastrow_kernel<<<nblocks, NTHREADS>>>(
        x, tau, freqs,
        phi_w0, phi_b0, phi_w1, phi_b1, phi_w2, phi_b2,
        psi_w0, psi_b0, psi_w1, psi_b1, psi_w2, psi_b2,
        rho_w0, rho_b0, rho_w1, rho_b1, rho_w2, rho_b2,
        tp_w0, tp_b0, tp_w1, tp_b1,
        out, Btot);
}

// round 2
// speedup vs baseline: 3.6379x; 3.6379x over previous
#include <cuda_runtime.h>
#include <math.h>

#define NPART 16
#define DDIM 3
#define HID 64
#define DLAT 5
#define TEMB 16
#define NFREQ 8
#define NPAIR 120
#define RHOIN 28
#define NTHREADS 128
#define BPB 4

// ---- dynamic smem layout (float offsets) ----
#define OFF_PSI_W1T 0          // [16][64][4] k-tiled transposed W1 (4096)
#define OFF_PHI_W1T 4096       // (4096)
#define OFF_H0S     8192       // psi h0: [kt][120] float4 (7680) ; phi h0 aliases [kt][16] float4
#define OFF_PSI_W0  15872      // [6][64] (384)
#define OFF_PSI_B0  16256      // (64)
#define OFF_PSI_B1  16320      // (64)
#define OFF_PSI_W2  16384      // [64][5] (320)
#define OFF_PSI_B2  16704      // (8)
#define OFF_PHI_W0  16712      // [3][64] (192)
#define OFF_PHI_B0  16904      // (64)
#define OFF_PHI_B1  16968      // (64)
#define OFF_PHI_W2  17032      // (320)
#define OFF_PHI_B2  17352      // (8)
#define OFF_X       17360      // (48)
#define OFF_GATE    17408      // (120)
#define OFF_RED     17528      // 14*4 (56)
#define OFF_RHOIN   17584      // (28)
#define OFF_RH0     17612      // (64)
#define OFF_TF      17676      // (17)
#define OFF_HT      17693      // (16)
#define OFF_MISC    17709      // (3)
#define SMEM_FLOATS 17712
#define SMEM_BYTES  (SMEM_FLOATS * 4)

__device__ __forceinline__ float gelu_f(float x) {
    return 0.5f * x * (1.0f + erff(x * 0.70710678118654752f));
}

__device__ __forceinline__ float blockReduceSum(float v, float* sRed) {
    const int tid = threadIdx.x;
    #pragma unroll
    for (int o = 16; o > 0; o >>= 1)
        v += __shfl_down_sync(0xffffffffu, v, o);
    if ((tid & 31) == 0) sRed[tid >> 5] = v;
    __syncthreads();
    float r = sRed[0] + sRed[1] + sRed[2] + sRed[3];
    __syncthreads();
    return r;
}

__global__ __launch_bounds__(NTHREADS, 3)
void tau_jastrow_kernel(
    const float* __restrict__ x, const float* __restrict__ tau, const float* __restrict__ freqs,
    const float* __restrict__ phi_w0, const float* __restrict__ phi_b0,
    const float* __restrict__ phi_w1, const float* __restrict__ phi_b1,
    const float* __restrict__ phi_w2, const float* __restrict__ phi_b2,
    const float* __restrict__ psi_w0, const float* __restrict__ psi_b0,
    const float* __restrict__ psi_w1, const float* __restrict__ psi_b1,
    const float* __restrict__ psi_w2, const float* __restrict__ psi_b2,
    const float* __restrict__ rho_w0, const float* __restrict__ rho_b0,
    const float* __restrict__ rho_w1, const float* __restrict__ rho_b1,
    const float* __restrict__ rho_w2, const float* __restrict__ rho_b2,
    const float* __restrict__ tp_w0, const float* __restrict__ tp_b0,
    const float* __restrict__ tp_w1, const float* __restrict__ tp_b1,
    float* __restrict__ out, int Btot)
{
    extern __shared__ float sm[];
    const int tid = threadIdx.x;

    // ---- preload weights (once per block) ----
    for (int idx = tid; idx < HID * HID; idx += NTHREADS) {
        int k = idx >> 6, j = idx & 63;
        int dst = (k >> 2) * 256 + j * 4 + (k & 3);
        sm[OFF_PSI_W1T + dst] = psi_w1[idx];
        sm[OFF_PHI_W1T + dst] = phi_w1[idx];
    }
    for (int i = tid; i < 6 * HID; i += NTHREADS) sm[OFF_PSI_W0 + i] = psi_w0[i];
    for (int i = tid; i < 3 * HID; i += NTHREADS) sm[OFF_PHI_W0 + i] = phi_w0[i];
    for (int i = tid; i < HID * DLAT; i += NTHREADS) {
        sm[OFF_PSI_W2 + i] = psi_w2[i];
        sm[OFF_PHI_W2 + i] = phi_w2[i];
    }
    if (tid < HID) {
        sm[OFF_PSI_B0 + tid] = psi_b0[tid]; sm[OFF_PSI_B1 + tid] = psi_b1[tid];
        sm[OFF_PHI_B0 + tid] = phi_b0[tid]; sm[OFF_PHI_B1 + tid] = phi_b1[tid];
    }
    if (tid < DLAT) {
        sm[OFF_PSI_B2 + tid] = psi_b2[tid];
        sm[OFF_PHI_B2 + tid] = phi_b2[tid];
    }

    // ---- pair indices (triu k=1 row-major) ----
    int pi = 0, pj = 0;
    {
        int p2 = tid, i2 = 0, cnt = NPART - 1;
        while (cnt > 0 && p2 >= cnt) { p2 -= cnt; i2++; cnt--; }
        pi = i2; pj = i2 + 1 + p2;
        if (pj >= NPART) pj = NPART - 1;
    }
    const bool active = (tid < NPAIR);
    const float gamma = ((pi < NPART / 2) == (pj < NPART / 2))
                        ? (1.0f / (DDIM + 1)) : (1.0f / (DDIM - 1));

    const int base = blockIdx.x * BPB;
    for (int b = base; b < base + BPB && b < Btot; ++b) {
        if (tid < NPART * DDIM) sm[OFF_X + tid] = x[(size_t)b * (NPART * DDIM) + tid];
        __syncthreads();

        float vals[14];
        #pragma unroll
        for (int v = 0; v < 14; v++) vals[v] = 0.f;

        // ================= Phase A: psi pair features + h0 =================
        if (active) {
            float d0 = sm[OFF_X + pi * 3 + 0] - sm[OFF_X + pj * 3 + 0];
            float d1 = sm[OFF_X + pi * 3 + 1] - sm[OFF_X + pj * 3 + 1];
            float d2 = sm[OFF_X + pi * 3 + 2] - sm[OFF_X + pj * 3 + 2];
            float r2 = d0 * d0 + d1 * d1 + d2 * d2;
            float r = sqrtf(r2 + 1.1920929e-7f);
            float rt2 = r2 + 0.04f;
            float u = rt2 * 25.0f;
            float feat[6];
            float s1v = log1pf(u);
            feat[0] = s1v;
            feat[1] = r2 / rt2;
            feat[2] = u * expf(-u);
            feat[3] = expf(-0.25f * s1v);
            feat[4] = expf(-s1v);
            feat[5] = expf(-4.0f * s1v);
            float gatev = r2 / (r2 + 0.09f);
            sm[OFF_GATE + tid] = gatev;
            vals[5] = gatev;
            vals[6] = s1v;
            vals[7] = gamma * r * expf(-r);

            const float4* w0 = (const float4*)(sm + OFF_PSI_W0);
            const float4* b0 = (const float4*)(sm + OFF_PSI_B0);
            float4* h0w = (float4*)(sm + OFF_H0S);
            #pragma unroll 2
            for (int kt = 0; kt < 16; kt++) {
                float4 a = b0[kt];
                #pragma unroll
                for (int i = 0; i < 6; i++) {
                    float4 w = w0[i * 16 + kt];
                    a.x += feat[i] * w.x; a.y += feat[i] * w.y;
                    a.z += feat[i] * w.z; a.w += feat[i] * w.w;
                }
                a.x = gelu_f(a.x); a.y = gelu_f(a.y);
                a.z = gelu_f(a.z); a.w = gelu_f(a.w);
                h0w[kt * 120 + tid] = a;
            }
        }
        __syncthreads();

        // ================= Phase B: psi h1 GEMM (120x64 @ 64x64) =================
        {
            const int rg = tid >> 4, cg = tid & 15;
            const int r0 = rg * 15;
            float acc[15][4];
            float b1c[4];
            #pragma unroll
            for (int c = 0; c < 4; c++) b1c[c] = sm[OFF_PSI_B1 + cg + 16 * c];
            #pragma unroll
            for (int r = 0; r < 15; r++)
                #pragma unroll
                for (int c = 0; c < 4; c++) acc[r][c] = b1c[c];

            const float4* w1t = (const float4*)(sm + OFF_PSI_W1T);
            const float4* h0 = (const float4*)(sm + OFF_H0S);
            #pragma unroll 1
            for (int kt = 0; kt < 16; kt++) {
                float4 bv0 = w1t[kt * 64 + cg];
                float4 bv1 = w1t[kt * 64 + cg + 16];
                float4 bv2 = w1t[kt * 64 + cg + 32];
                float4 bv3 = w1t[kt * 64 + cg + 48];
                #pragma unroll
                for (int r = 0; r < 15; r++) {
                    float4 a = h0[kt * 120 + r0 + r];
                    acc[r][0] += a.x * bv0.x; acc[r][0] += a.y * bv0.y;
                    acc[r][0] += a.z * bv0.z; acc[r][0] += a.w * bv0.w;
                    acc[r][1] += a.x * bv1.x; acc[r][1] += a.y * bv1.y;
                    acc[r][1] += a.z * bv1.z; acc[r][1] += a.w * bv1.w;
                    acc[r][2] += a.x * bv2.x; acc[r][2] += a.y * bv2.y;
                    acc[r][2] += a.z * bv2.z; acc[r][2] += a.w * bv2.w;
                    acc[r][3] += a.x * bv3.x; acc[r][3] += a.y * bv3.y;
                    acc[r][3] += a.z * bv3.z; acc[r][3] += a.w * bv3.w;
                }
            }
            // epilogue: gelu -> W2 -> gate -> partial sums
            float w2r[4][5];
            #pragma unroll
            for (int c = 0; c < 4; c++)
                #pragma unroll
                for (int d = 0; d < 5; d++)
                    w2r[c][d] = sm[OFF_PSI_W2 + (cg + 16 * c) * 5 + d];
            #pragma unroll
            for (int r = 0; r < 15; r++) {
                float gt = sm[OFF_GATE + r0 + r];
                #pragma unroll
                for (int c = 0; c < 4; c++) {
                    float g = gelu_f(acc[r][c]) * gt;
                    #pragma unroll
                    for (int d = 0; d < 5; d++) vals[d] += g * w2r[c][d];
                }
            }
        }
        __syncthreads();  // h0s region about to be reused by phi

        // ================= Phi h0 (aliases h0s region) + time features =================
        {
            int p = tid >> 3, c3 = tid & 7;
            float xv0 = sm[OFF_X + p * 3 + 0];
            float xv1 = sm[OFF_X + p * 3 + 1];
            float xv2 = sm[OFF_X + p * 3 + 2];
            const float4* w0 = (const float4*)(sm + OFF_PHI_W0);
            const float4* b0 = (const float4*)(sm + OFF_PHI_B0);
            float4* h0w = (float4*)(sm + OFF_H0S);
            #pragma unroll
            for (int t = 0; t < 2; t++) {
                int kt = 2 * c3 + t;
                float4 a = b0[kt];
                float4 w;
                w = w0[0 * 16 + kt];
                a.x += xv0 * w.x; a.y += xv0 * w.y; a.z += xv0 * w.z; a.w += xv0 * w.w;
                w = w0[1 * 16 + kt];
                a.x += xv1 * w.x; a.y += xv1 * w.y; a.z += xv1 * w.z; a.w += xv1 * w.w;
                w = w0[2 * 16 + kt];
                a.x += xv2 * w.x; a.y += xv2 * w.y; a.z += xv2 * w.z; a.w += xv2 * w.w;
                a.x = gelu_f(a.x); a.y = gelu_f(a.y);
                a.z = gelu_f(a.z); a.w = gelu_f(a.w);
                h0w[kt * 16 + p] = a;
            }
        }
        float tb = tau[b];
        if (tid == 0) sm[OFF_TF + 0] = tb;
        if (tid < NFREQ) {
            float ft = freqs[tid] * tb;
            sm[OFF_TF + 1 + tid] = sinf(ft);
            sm[OFF_TF + 1 + NFREQ + tid] = cosf(ft);
        }
        __syncthreads();

        // ================= Phi h1 GEMM (16x64 @ 64x64) =================
        {
            int row = tid >> 3, cg = tid & 7;
            float acc8[8];
            #pragma unroll
            for (int c = 0; c < 8; c++) acc8[c] = sm[OFF_PHI_B1 + cg + 8 * c];
            const float4* w1t = (const float4*)(sm + OFF_PHI_W1T);
            const float4* h0 = (const float4*)(sm + OFF_H0S);
            #pragma unroll 2
            for (int kt = 0; kt < 16; kt++) {
                float4 a = h0[kt * 16 + row];
                #pragma unroll
                for (int c = 0; c < 8; c++) {
                    float4 bv = w1t[kt * 64 + cg + 8 * c];
                    acc8[c] += a.x * bv.x; acc8[c] += a.y * bv.y;
                    acc8[c] += a.z * bv.z; acc8[c] += a.w * bv.w;
                }
            }
            #pragma unroll
            for (int c = 0; c < 8; c++) {
                float g = gelu_f(acc8[c]);
                #pragma unroll
                for (int d = 0; d < 5; d++)
                    vals[8 + d] += g * sm[OFF_PHI_W2 + (cg + 8 * c) * 5 + d];
            }
        }
        if (tid < NPART * DDIM) {
            float xv = sm[OFF_X + tid];
            vals[13] = xv * xv;
        }

        // ================= fused 14-value block reduction =================
        {
            const int lane = tid & 31, wid = tid >> 5;
            #pragma unroll
            for (int v = 0; v < 14; v++) {
                float t = vals[v];
                #pragma unroll
                for (int o = 16; o > 0; o >>= 1)
                    t += __shfl_down_sync(0xffffffffu, t, o);
                if (lane == 0) sm[OFF_RED + v * 4 + wid] = t;
            }
        }
        __syncthreads();
        if (tid < 14) {
            float s = sm[OFF_RED + tid * 4 + 0] + sm[OFF_RED + tid * 4 + 1]
                    + sm[OFF_RED + tid * 4 + 2] + sm[OFF_RED + tid * 4 + 3];
            if (tid < 5) {
                float gs = sm[OFF_RED + 20] + sm[OFF_RED + 21]
                         + sm[OFF_RED + 22] + sm[OFF_RED + 23];
                sm[OFF_RHOIN + 5 + tid] = (s + sm[OFF_PSI_B2 + tid] * gs) * (1.0f / NPAIR);
            } else if (tid == 6) {
                sm[OFF_RHOIN + 11] = s * (1.0f / NPAIR);
            } else if (tid == 7) {
                sm[OFF_MISC + 0] = s;   // cusp sum
            } else if (tid >= 8 && tid < 13) {
                sm[OFF_RHOIN + (tid - 8)] = s * (1.0f / NPART) + sm[OFF_PHI_B2 + tid - 8];
            } else if (tid == 13) {
                sm[OFF_RHOIN + 10] = s * (1.0f / (NPART * DDIM));
            }
        }
        // temb layer 1 (sTF synced by the reduction barrier)
        if (tid < TEMB) {
            float a = tp_b0[tid];
            #pragma unroll
            for (int i2 = 0; i2 < 2 * NFREQ + 1; i2++)
                a += sm[OFF_TF + i2] * tp_w0[i2 * TEMB + tid];
            sm[OFF_HT + tid] = gelu_f(a);
        }
        __syncthreads();
        if (tid < TEMB) {
            float a = tp_b1[tid];
            #pragma unroll
            for (int i2 = 0; i2 < TEMB; i2++)
                a += sm[OFF_HT + i2] * tp_w1[i2 * TEMB + tid];
            sm[OFF_RHOIN + 12 + tid] = a;
        }
        __syncthreads();

        // ================= rho MLP (28 -> 64 -> 64 -> 1) =================
        if (tid < HID) {
            float a = rho_b0[tid];
            #pragma unroll 4
            for (int i2 = 0; i2 < RHOIN; i2++)
                a += sm[OFF_RHOIN + i2] * rho_w0[i2 * HID + tid];
            sm[OFF_RH0 + tid] = gelu_f(a);
        }
        __syncthreads();
        float part = 0.f;
        if (tid < HID) {
            float a = rho_b1[tid];
            #pragma unroll 4
            for (int k = 0; k < HID; k++)
                a += sm[OFF_RH0 + k] * rho_w1[k * HID + tid];
            part = gelu_f(a) * rho_w2[tid];
        }
        float osum = blockReduceSum(part, sm + OFF_RED);
        if (tid == 0) out[b] = osum + rho_b2[0] + sm[OFF_MISC + 0];
        __syncthreads();
    }
}

extern "C" void kernel_launch(void* const* d_in, const int* in_sizes, int n_in,
                              void* d_out, int out_size) {
    const float* x      = (const float*)d_in[0];
    const float* tau    = (const float*)d_in[1];
    const float* freqs  = (const float*)d_in[2];
    const float* phi_w0 = (const float*)d_in[3];
    const float* phi_b0 = (const float*)d_in[4];
    const float* phi_w1 = (const float*)d_in[5];
    const float* phi_b1 = (const float*)d_in[6];
    const float* phi_w2 = (const float*)d_in[7];
    const float* phi_b2 = (const float*)d_in[8];
    const float* psi_w0 = (const float*)d_in[9];
    const float* psi_b0 = (const float*)d_in[10];
    const float* psi_w1 = (const float*)d_in[11];
    const float* psi_b1 = (const float*)d_in[12];
    const float* psi_w2 = (const float*)d_in[13];
    const float* psi_b2 = (const float*)d_in[14];
    const float* rho_w0 = (const float*)d_in[15];
    const float* rho_b0 = (const float*)d_in[16];
    const float* rho_w1 = (const float*)d_in[17];
    const float* rho_b1 = (const float*)d_in[18];
    const float* rho_w2 = (const float*)d_in[19];
    const float* rho_b2 = (const float*)d_in[20];
    const float* tp_w0  = (const float*)d_in[21];
    const float* tp_b0  = (const float*)d_in[22];
    const float* tp_w1  = (const float*)d_in[23];
    const float* tp_b1  = (const float*)d_in[24];
    float* out = (float*)d_out;

    const int Btot = in_sizes[1];
    const int nblocks = (Btot + BPB - 1) / BPB;

    cudaFuncSetAttribute(tau_jastrow_kernel,
                         cudaFuncAttributeMaxDynamicSharedMemorySize, SMEM_BYTES);

    tau_jastrow_kernel<<<nblocks, NTHREADS, SMEM_BYTES>>>(
        x, tau, freqs,
        phi_w0, phi_b0, phi_w1, phi_b1, phi_w2, phi_b2,
        psi_w0, psi_b0, psi_w1, psi_b1, psi_w2, psi_b2,
        rho_w0, rho_b0, rho_w1, rho_b1, rho_w2, rho_b2,
        tp_w0, tp_b0, tp_w1, tp_b1,
        out, Btot);
}

// round 4
// speedup vs baseline: 4.5735x; 1.2572x over previous
#include <cuda_runtime.h>
#include <math.h>

#define NPART 16
#define DDIM 3
#define HID 64
#define DLAT 5
#define TEMB 16
#define NFREQ 8
#define NPAIR 120
#define RHOIN 28
#define NTHREADS 128
#define BPB 4

// ---- dynamic smem layout (float offsets) ----
#define OFF_PSI_W1T 0          // [16][64][4] k-tiled transposed psi W1 (4096)
#define OFF_H0S     4096       // psi h0 transposed [kt][kc][128] (8192); phi h0 [kt][16]f4 aliases at +0; phi W1T aliases at +4096
#define OFF_PHI_W1T (OFF_H0S + 4096)
#define OFF_PSI_W0  12288      // [6][64] (384)
#define OFF_PSI_B0  12672      // (64)
#define OFF_PSI_B1  12736      // (64)
#define OFF_PSI_W2  12800      // [64][5] (320)
#define OFF_PSI_B2  13120      // (8)
#define OFF_PHI_W0  13128      // [3][64] (192)
#define OFF_PHI_B0  13320      // (64)
#define OFF_PHI_B1  13384      // (64)
#define OFF_PHI_W2  13448      // (320)
#define OFF_PHI_B2  13768      // (8)
#define OFF_X       13776      // (48)
#define OFF_GATE    13824      // (128, rows 120..127 = 0)
#define OFF_RED     13952      // 14*4 (56)
#define OFF_RHOIN   14008      // (28)
#define OFF_RH0     14036      // (64)
#define OFF_TF      14100      // (17)
#define OFF_HT      14117      // (16)
#define OFF_MISC    14133      // (3)
#define SMEM_FLOATS 14136
#define SMEM_BYTES  (SMEM_FLOATS * 4)

__device__ __forceinline__ float gelu_f(float x) {
    return 0.5f * x * (1.0f + erff(x * 0.70710678118654752f));
}

__device__ __forceinline__ unsigned long long pack_dup(float b) {
    unsigned long long r;
    asm("mov.b64 %0, {%1, %1};" : "=l"(r) : "f"(b));
    return r;
}
__device__ __forceinline__ void ffma2(unsigned long long& d, unsigned long long a, unsigned long long b) {
    asm("fma.rn.f32x2 %0, %1, %2, %0;" : "+l"(d) : "l"(a), "l"(b));
}
__device__ __forceinline__ float2 unpack2(unsigned long long v) {
    float2 f;
    asm("mov.b64 {%0, %1}, %2;" : "=f"(f.x), "=f"(f.y) : "l"(v));
    return f;
}

__device__ __forceinline__ float blockReduceSum(float v, float* sRed) {
    const int tid = threadIdx.x;
    #pragma unroll
    for (int o = 16; o > 0; o >>= 1)
        v += __shfl_down_sync(0xffffffffu, v, o);
    if ((tid & 31) == 0) sRed[tid >> 5] = v;
    __syncthreads();
    float r = sRed[0] + sRed[1] + sRed[2] + sRed[3];
    __syncthreads();
    return r;
}

__global__ __launch_bounds__(NTHREADS, 4)
void tau_jastrow_kernel(
    const float* __restrict__ x, const float* __restrict__ tau, const float* __restrict__ freqs,
    const float* __restrict__ phi_w0, const float* __restrict__ phi_b0,
    const float* __restrict__ phi_w1, const float* __restrict__ phi_b1,
    const float* __restrict__ phi_w2, const float* __restrict__ phi_b2,
    const float* __restrict__ psi_w0, const float* __restrict__ psi_b0,
    const float* __restrict__ psi_w1, const float* __restrict__ psi_b1,
    const float* __restrict__ psi_w2, const float* __restrict__ psi_b2,
    const float* __restrict__ rho_w0, const float* __restrict__ rho_b0,
    const float* __restrict__ rho_w1, const float* __restrict__ rho_b1,
    const float* __restrict__ rho_w2, const float* __restrict__ rho_b2,
    const float* __restrict__ tp_w0, const float* __restrict__ tp_b0,
    const float* __restrict__ tp_w1, const float* __restrict__ tp_b1,
    float* __restrict__ out, int Btot)
{
    extern __shared__ float sm[];
    const int tid = threadIdx.x;

    // ---- preload psi weights (once per block) ----
    for (int idx = tid; idx < HID * HID; idx += NTHREADS) {
        int k = idx >> 6, j = idx & 63;
        sm[OFF_PSI_W1T + (k >> 2) * 256 + j * 4 + (k & 3)] = psi_w1[idx];
    }
    for (int i = tid; i < 6 * HID; i += NTHREADS) sm[OFF_PSI_W0 + i] = psi_w0[i];
    for (int i = tid; i < 3 * HID; i += NTHREADS) sm[OFF_PHI_W0 + i] = phi_w0[i];
    for (int i = tid; i < HID * DLAT; i += NTHREADS) {
        sm[OFF_PSI_W2 + i] = psi_w2[i];
        sm[OFF_PHI_W2 + i] = phi_w2[i];
    }
    if (tid < HID) {
        sm[OFF_PSI_B0 + tid] = psi_b0[tid]; sm[OFF_PSI_B1 + tid] = psi_b1[tid];
        sm[OFF_PHI_B0 + tid] = phi_b0[tid]; sm[OFF_PHI_B1 + tid] = phi_b1[tid];
    }
    if (tid < DLAT) {
        sm[OFF_PSI_B2 + tid] = psi_b2[tid];
        sm[OFF_PHI_B2 + tid] = phi_b2[tid];
    }
    if (tid >= NPAIR) sm[OFF_GATE + tid] = 0.f;   // padded rows: gate = 0, persists

    // ---- pair indices (triu k=1 row-major) ----
    int pi = 0, pj = 0;
    {
        int p2 = tid, i2 = 0, cnt = NPART - 1;
        while (cnt > 0 && p2 >= cnt) { p2 -= cnt; i2++; cnt--; }
        pi = i2; pj = i2 + 1 + p2;
        if (pj >= NPART) pj = NPART - 1;
    }
    const bool active = (tid < NPAIR);
    const float gamma = ((pi < NPART / 2) == (pj < NPART / 2))
                        ? (1.0f / (DDIM + 1)) : (1.0f / (DDIM - 1));

    const int base = blockIdx.x * BPB;
    for (int b = base; b < base + BPB && b < Btot; ++b) {
        if (tid < NPART * DDIM) sm[OFF_X + tid] = x[(size_t)b * (NPART * DDIM) + tid];
        __syncthreads();

        float vals[14];
        #pragma unroll
        for (int v = 0; v < 14; v++) vals[v] = 0.f;

        // ================= Phase A: psi pair features + h0 (transposed store) =================
        if (active) {
            float d0 = sm[OFF_X + pi * 3 + 0] - sm[OFF_X + pj * 3 + 0];
            float d1 = sm[OFF_X + pi * 3 + 1] - sm[OFF_X + pj * 3 + 1];
            float d2 = sm[OFF_X + pi * 3 + 2] - sm[OFF_X + pj * 3 + 2];
            float r2 = d0 * d0 + d1 * d1 + d2 * d2;
            float r = sqrtf(r2 + 1.1920929e-7f);
            float rt2 = r2 + 0.04f;
            float u = rt2 * 25.0f;
            float tt = __fdividef(1.0f, 1.0f + u);
            float feat[6];
            float s1v = -__logf(tt);
            feat[0] = s1v;
            feat[1] = __fdividef(r2, rt2);
            feat[2] = u * __expf(-u);
            feat[4] = tt;                        // exp(-s1) = (1+u)^-1
            float t2 = tt * tt;
            feat[5] = t2 * t2;                   // exp(-4 s1)
            feat[3] = sqrtf(sqrtf(tt));          // exp(-0.25 s1)
            float gatev = __fdividef(r2, r2 + 0.09f);
            sm[OFF_GATE + tid] = gatev;
            vals[5] = gatev;
            vals[6] = s1v;
            vals[7] = gamma * r * __expf(-r);

            const float4* w0 = (const float4*)(sm + OFF_PSI_W0);
            const float4* b0 = (const float4*)(sm + OFF_PSI_B0);
            #pragma unroll 2
            for (int kt = 0; kt < 16; kt++) {
                float4 a = b0[kt];
                #pragma unroll
                for (int i = 0; i < 6; i++) {
                    float4 w = w0[i * 16 + kt];
                    a.x += feat[i] * w.x; a.y += feat[i] * w.y;
                    a.z += feat[i] * w.z; a.w += feat[i] * w.w;
                }
                float* dst = sm + OFF_H0S + kt * 512 + tid;
                dst[0]   = gelu_f(a.x);
                dst[128] = gelu_f(a.y);
                dst[256] = gelu_f(a.z);
                dst[384] = gelu_f(a.w);
            }
        } else {
            // zero padded rows so packed GEMM sees finite values
            #pragma unroll
            for (int kt = 0; kt < 16; kt++) {
                float* dst = sm + OFF_H0S + kt * 512 + tid;
                dst[0] = 0.f; dst[128] = 0.f; dst[256] = 0.f; dst[384] = 0.f;
            }
        }
        __syncthreads();

        // ================= psi h1 GEMM, packed f32x2 (128x64 @ 64x64) =================
        {
            const int rg = tid >> 4, cg = tid & 15;
            const int r0 = rg * 16;
            unsigned long long acc[8][4];
            #pragma unroll
            for (int c = 0; c < 4; c++) {
                unsigned long long bi = pack_dup(sm[OFF_PSI_B1 + cg + 16 * c]);
                #pragma unroll
                for (int q = 0; q < 8; q++) acc[q][c] = bi;
            }
            const float4* w1t4 = (const float4*)(sm + OFF_PSI_W1T);
            #pragma unroll 1
            for (int kt = 0; kt < 16; kt++) {
                float4 bv0 = w1t4[kt * 64 + cg];
                float4 bv1 = w1t4[kt * 64 + cg + 16];
                float4 bv2 = w1t4[kt * 64 + cg + 32];
                float4 bv3 = w1t4[kt * 64 + cg + 48];
                const float* hbase = sm + OFF_H0S + kt * 512 + r0;
                #define KC_STEP(kc, comp)                                           \
                {                                                                   \
                    unsigned long long b20 = pack_dup(bv0.comp);                    \
                    unsigned long long b21 = pack_dup(bv1.comp);                    \
                    unsigned long long b22 = pack_dup(bv2.comp);                    \
                    unsigned long long b23 = pack_dup(bv3.comp);                    \
                    const unsigned long long* ap =                                  \
                        (const unsigned long long*)(hbase + (kc) * 128);            \
                    _Pragma("unroll")                                               \
                    for (int q = 0; q < 8; q++) {                                   \
                        unsigned long long a2 = ap[q];                              \
                        ffma2(acc[q][0], a2, b20);                                  \
                        ffma2(acc[q][1], a2, b21);                                  \
                        ffma2(acc[q][2], a2, b22);                                  \
                        ffma2(acc[q][3], a2, b23);                                  \
                    }                                                               \
                }
                KC_STEP(0, x) KC_STEP(1, y) KC_STEP(2, z) KC_STEP(3, w)
                #undef KC_STEP
            }
            // epilogue: gelu -> gate -> W2 -> partial sums
            #pragma unroll
            for (int c = 0; c < 4; c++) {
                const int j = cg + 16 * c;
                float w2r[5];
                #pragma unroll
                for (int d = 0; d < 5; d++) w2r[d] = sm[OFF_PSI_W2 + j * 5 + d];
                #pragma unroll
                for (int q = 0; q < 8; q++) {
                    float2 v = unpack2(acc[q][c]);
                    float g = gelu_f(v.x) * sm[OFF_GATE + r0 + 2 * q]
                            + gelu_f(v.y) * sm[OFF_GATE + r0 + 2 * q + 1];
                    #pragma unroll
                    for (int d = 0; d < 5; d++) vals[d] += g * w2r[d];
                }
            }
        }
        __syncthreads();  // h0s region about to be reused by phi

        // ===== phi W1T reload (into h0s upper half) + phi h0 + time features =====
        {
            const float4* gw = (const float4*)phi_w1;
            #pragma unroll
            for (int i = 0; i < 8; i++) {
                int idx4 = tid + 128 * i;          // float4 index 0..1023
                float4 v = gw[idx4];
                int k = idx4 >> 4;
                int j0 = (idx4 & 15) * 4;
                float* d = sm + OFF_PHI_W1T + (k >> 2) * 256 + (k & 3) + j0 * 4;
                d[0] = v.x; d[4] = v.y; d[8] = v.z; d[12] = v.w;
            }
        }
        {
            int p = tid >> 3, c3 = tid & 7;
            float xv0 = sm[OFF_X + p * 3 + 0];
            float xv1 = sm[OFF_X + p * 3 + 1];
            float xv2 = sm[OFF_X + p * 3 + 2];
            const float4* w0 = (const float4*)(sm + OFF_PHI_W0);
            const float4* b0 = (const float4*)(sm + OFF_PHI_B0);
            float4* h0w = (float4*)(sm + OFF_H0S);
            #pragma unroll
            for (int t = 0; t < 2; t++) {
                int kt = 2 * c3 + t;
                float4 a = b0[kt];
                float4 w;
                w = w0[0 * 16 + kt];
                a.x += xv0 * w.x; a.y += xv0 * w.y; a.z += xv0 * w.z; a.w += xv0 * w.w;
                w = w0[1 * 16 + kt];
                a.x += xv1 * w.x; a.y += xv1 * w.y; a.z += xv1 * w.z; a.w += xv1 * w.w;
                w = w0[2 * 16 + kt];
                a.x += xv2 * w.x; a.y += xv2 * w.y; a.z += xv2 * w.z; a.w += xv2 * w.w;
                a.x = gelu_f(a.x); a.y = gelu_f(a.y);
                a.z = gelu_f(a.z); a.w = gelu_f(a.w);
                h0w[kt * 16 + p] = a;
            }
        }
        float tb = tau[b];
        if (tid == 0) sm[OFF_TF + 0] = tb;
        if (tid < NFREQ) {
            float ft = freqs[tid] * tb;
            sm[OFF_TF + 1 + tid] = __sinf(ft);
            sm[OFF_TF + 1 + NFREQ + tid] = __cosf(ft);
        }
        __syncthreads();

        // ================= Phi h1 GEMM (16x64 @ 64x64) =================
        {
            int row = tid >> 3, cg = tid & 7;
            float acc8[8];
            #pragma unroll
            for (int c = 0; c < 8; c++) acc8[c] = sm[OFF_PHI_B1 + cg + 8 * c];
            const float4* w1t = (const float4*)(sm + OFF_PHI_W1T);
            const float4* h0 = (const float4*)(sm + OFF_H0S);
            #pragma unroll 2
            for (int kt = 0; kt < 16; kt++) {
                float4 a = h0[kt * 16 + row];
                #pragma unroll
                for (int c = 0; c < 8; c++) {
                    float4 bv = w1t[kt * 64 + cg + 8 * c];
                    acc8[c] += a.x * bv.x; acc8[c] += a.y * bv.y;
                    acc8[c] += a.z * bv.z; acc8[c] += a.w * bv.w;
                }
            }
            #pragma unroll
            for (int c = 0; c < 8; c++) {
                float g = gelu_f(acc8[c]);
                #pragma unroll
                for (int d = 0; d < 5; d++)
                    vals[8 + d] += g * sm[OFF_PHI_W2 + (cg + 8 * c) * 5 + d];
            }
        }
        if (tid < NPART * DDIM) {
            float xv = sm[OFF_X + tid];
            vals[13] = xv * xv;
        }

        // ================= fused 14-value block reduction =================
        {
            const int lane = tid & 31, wid = tid >> 5;
            #pragma unroll
            for (int v = 0; v < 14; v++) {
                float t = vals[v];
                #pragma unroll
                for (int o = 16; o > 0; o >>= 1)
                    t += __shfl_down_sync(0xffffffffu, t, o);
                if (lane == 0) sm[OFF_RED + v * 4 + wid] = t;
            }
        }
        __syncthreads();
        if (tid < 14) {
            float s = sm[OFF_RED + tid * 4 + 0] + sm[OFF_RED + tid * 4 + 1]
                    + sm[OFF_RED + tid * 4 + 2] + sm[OFF_RED + tid * 4 + 3];
            if (tid < 5) {
                float gs = sm[OFF_RED + 20] + sm[OFF_RED + 21]
                         + sm[OFF_RED + 22] + sm[OFF_RED + 23];
                sm[OFF_RHOIN + 5 + tid] = (s + sm[OFF_PSI_B2 + tid] * gs) * (1.0f / NPAIR);
            } else if (tid == 6) {
                sm[OFF_RHOIN + 11] = s * (1.0f / NPAIR);
            } else if (tid == 7) {
                sm[OFF_MISC + 0] = s;   // cusp sum
            } else if (tid >= 8 && tid < 13) {
                sm[OFF_RHOIN + (tid - 8)] = s * (1.0f / NPART) + sm[OFF_PHI_B2 + tid - 8];
            } else if (tid == 13) {
                sm[OFF_RHOIN + 10] = s * (1.0f / (NPART * DDIM));
            }
        }
        // temb layer 1 (sTF synced by the reduction barrier)
        if (tid < TEMB) {
            float a = tp_b0[tid];
            #pragma unroll
            for (int i2 = 0; i2 < 2 * NFREQ + 1; i2++)
                a += sm[OFF_TF + i2] * tp_w0[i2 * TEMB + tid];
            sm[OFF_HT + tid] = gelu_f(a);
        }
        __syncthreads();
        if (tid < TEMB) {
            float a = tp_b1[tid];
            #pragma unroll
            for (int i2 = 0; i2 < TEMB; i2++)
                a += sm[OFF_HT + i2] * tp_w1[i2 * TEMB + tid];
            sm[OFF_RHOIN + 12 + tid] = a;
        }
        __syncthreads();

        // ================= rho MLP (28 -> 64 -> 64 -> 1) =================
        if (tid < HID) {
            float a = rho_b0[tid];
            #pragma unroll 4
            for (int i2 = 0; i2 < RHOIN; i2++)
                a += sm[OFF_RHOIN + i2] * rho_w0[i2 * HID + tid];
            sm[OFF_RH0 + tid] = gelu_f(a);
        }
        __syncthreads();
        float part = 0.f;
        if (tid < HID) {
            float a = rho_b1[tid];
            #pragma unroll 4
            for (int k = 0; k < HID; k++)
                a += sm[OFF_RH0 + k] * rho_w1[k * HID + tid];
            part = gelu_f(a) * rho_w2[tid];
        }
        float osum = blockReduceSum(part, sm + OFF_RED);
        if (tid == 0) out[b] = osum + rho_b2[0] + sm[OFF_MISC + 0];
        __syncthreads();
    }
}

extern "C" void kernel_launch(void* const* d_in, const int* in_sizes, int n_in,
                              void* d_out, int out_size) {
    const float* x      = (const float*)d_in[0];
    const float* tau    = (const float*)d_in[1];
    const float* freqs  = (const float*)d_in[2];
    const float* phi_w0 = (const float*)d_in[3];
    const float* phi_b0 = (const float*)d_in[4];
    const float* phi_w1 = (const float*)d_in[5];
    const float* phi_b1 = (const float*)d_in[6];
    const float* phi_w2 = (const float*)d_in[7];
    const float* phi_b2 = (const float*)d_in[8];
    const float* psi_w0 = (const float*)d_in[9];
    const float* psi_b0 = (const float*)d_in[10];
    const float* psi_w1 = (const float*)d_in[11];
    const float* psi_b1 = (const float*)d_in[12];
    const float* psi_w2 = (const float*)d_in[13];
    const float* psi_b2 = (const float*)d_in[14];
    const float* rho_w0 = (const float*)d_in[15];
    const float* rho_b0 = (const float*)d_in[16];
    const float* rho_w1 = (const float*)d_in[17];
    const float* rho_b1 = (const float*)d_in[18];
    const float* rho_w2 = (const float*)d_in[19];
    const float* rho_b2 = (const float*)d_in[20];
    const float* tp_w0  = (const float*)d_in[21];
    const float* tp_b0  = (const float*)d_in[22];
    const float* tp_w1  = (const float*)d_in[23];
    const float* tp_b1  = (const float*)d_in[24];
    float* out = (float*)d_out;

    const int Btot = in_sizes[1];
    const int nblocks = (Btot + BPB - 1) / BPB;

    cudaFuncSetAttribute(tau_jastrow_kernel,
                         cudaFuncAttributeMaxDynamicSharedMemorySize, SMEM_BYTES);

    tau_jastrow_kernel<<<nblocks, NTHREADS, SMEM_BYTES>>>(
        x, tau, freqs,
        phi_w0, phi_b0, phi_w1, phi_b1, phi_w2, phi_b2,
        psi_w0, psi_b0, psi_w1, psi_b1, psi_w2, psi_b2,
        rho_w0, rho_b0, rho_w1, rho_b1, rho_w2, rho_b2,
        tp_w0, tp_b0, tp_w1, tp_b1,
        out, Btot);
}

// round 5
// speedup vs baseline: 4.9819x; 1.0893x over previous
#include <cuda_runtime.h>
#include <math.h>

#define NPART 16
#define DDIM 3
#define HID 64
#define DLAT 5
#define TEMB 16
#define NFREQ 8
#define NPAIR 120
#define RHOIN 28
#define NTHREADS 128
#define BPB 4

typedef unsigned long long ull;

// ---- dynamic smem layout (float offsets) ----
#define OFF_PSI_W1T 0          // [16][64][4] k-tiled transposed psi W1 (4096)
#define OFF_H0S     4096       // psi h0 transposed [kt][kc][128] (8192); phi h0 [kt][16]f4 aliases at +0; phi W1T aliases at +4096
#define OFF_PHI_W1T (OFF_H0S + 4096)
#define OFF_PSI_W0  12288      // [6][64] (384)
#define OFF_PSI_B0  12672      // (64)
#define OFF_PSI_B1  12736      // (64)
#define OFF_PSI_W2  12800      // [64][5] (320)
#define OFF_PSI_B2  13120      // (8)
#define OFF_PHI_W0  13128      // [3][64] (192)
#define OFF_PHI_B0  13320      // (64)
#define OFF_PHI_B1  13384      // (64)
#define OFF_PHI_W2  13448      // (320)
#define OFF_PHI_B2  13768      // (8)
#define OFF_X       13776      // (48)
#define OFF_GATE    13824      // (128, rows 120..127 = 0)
#define OFF_RED     13952      // 14*4 (56)
#define OFF_RHOIN   14008      // (28)
#define OFF_RH0     14036      // (64)
#define OFF_TF      14100      // (17)
#define OFF_HT      14117      // (16)
#define OFF_MISC    14133      // (3)
#define SMEM_FLOATS 14136
#define SMEM_BYTES  (SMEM_FLOATS * 4)

// ---- packed f32x2 helpers ----
__device__ __forceinline__ ull pack2(float lo, float hi) {
    ull r; asm("mov.b64 %0, {%1, %2};" : "=l"(r) : "f"(lo), "f"(hi)); return r;
}
__device__ __forceinline__ ull dup2(float b) {
    ull r; asm("mov.b64 %0, {%1, %1};" : "=l"(r) : "f"(b)); return r;
}
__device__ __forceinline__ float2 unpack2(ull v) {
    float2 f; asm("mov.b64 {%0, %1}, %2;" : "=f"(f.x), "=f"(f.y) : "l"(v)); return f;
}
__device__ __forceinline__ void ffma2(ull& d, ull a, ull b) {
    asm("fma.rn.f32x2 %0, %1, %2, %0;" : "+l"(d) : "l"(a), "l"(b));
}
__device__ __forceinline__ ull fma2(ull a, ull b, ull c) {
    ull d; asm("fma.rn.f32x2 %0, %1, %2, %3;" : "=l"(d) : "l"(a), "l"(b), "l"(c)); return d;
}
__device__ __forceinline__ ull mul2(ull a, ull b) {
    ull d; asm("mul.rn.f32x2 %0, %1, %2;" : "=l"(d) : "l"(a), "l"(b)); return d;
}
__device__ __forceinline__ ull add2(ull a, ull b) {
    ull d; asm("add.rn.f32x2 %0, %1, %2;" : "=l"(d) : "l"(a), "l"(b)); return d;
}

// ---- gelu: A&S 7.1.26 erf (|err|<=1.5e-7), branchless:
//  gelu(x) = 0.5*((x+|x|) - |x|*p(t)*exp(-z^2)),  z=|x|/sqrt2, t=1/(1+0.3275911 z)
__device__ __forceinline__ float gelu_f(float x) {
    float ax = fabsf(x);
    float z = ax * 0.70710678118f;
    float t = __fdividef(1.0f, fmaf(0.3275911f, z, 1.0f));
    float p = t * fmaf(t, fmaf(t, fmaf(t, fmaf(t, 1.061405429f, -1.453152027f),
                         1.421413741f), -0.284496736f), 0.254829592f);
    float q = p * exp2f(-1.442695041f * z * z);
    return 0.5f * ((x + ax) - ax * q);
}

__device__ __forceinline__ ull gelu2(ull x2) {
    ull ax2;
    asm("and.b64 %0, %1, %2;" : "=l"(ax2) : "l"(x2), "l"(0x7fffffff7fffffffULL));
    ull z2 = mul2(ax2, dup2(0.70710678118f));
    float2 z = unpack2(z2);
    float tx = __fdividef(1.0f, fmaf(0.3275911f, z.x, 1.0f));
    float ty = __fdividef(1.0f, fmaf(0.3275911f, z.y, 1.0f));
    ull t2 = pack2(tx, ty);
    ull p2 = fma2(t2, dup2(1.061405429f), dup2(-1.453152027f));
    p2 = fma2(p2, t2, dup2(1.421413741f));
    p2 = fma2(p2, t2, dup2(-0.284496736f));
    p2 = fma2(p2, t2, dup2(0.254829592f));
    p2 = mul2(p2, t2);
    float2 m = unpack2(mul2(mul2(z2, z2), dup2(-1.442695041f)));
    ull q2 = mul2(p2, pack2(exp2f(m.x), exp2f(m.y)));
    ull s2 = add2(x2, ax2);                       // x + |x|
    ull w2 = mul2(ax2, q2);                       // |x| * q
    return fma2(w2, dup2(-0.5f), mul2(s2, dup2(0.5f)));
}

__device__ __forceinline__ float blockReduceSum(float v, float* sRed) {
    const int tid = threadIdx.x;
    #pragma unroll
    for (int o = 16; o > 0; o >>= 1)
        v += __shfl_down_sync(0xffffffffu, v, o);
    if ((tid & 31) == 0) sRed[tid >> 5] = v;
    __syncthreads();
    float r = sRed[0] + sRed[1] + sRed[2] + sRed[3];
    __syncthreads();
    return r;
}

__global__ __launch_bounds__(NTHREADS, 4)
void tau_jastrow_kernel(
    const float* __restrict__ x, const float* __restrict__ tau, const float* __restrict__ freqs,
    const float* __restrict__ phi_w0, const float* __restrict__ phi_b0,
    const float* __restrict__ phi_w1, const float* __restrict__ phi_b1,
    const float* __restrict__ phi_w2, const float* __restrict__ phi_b2,
    const float* __restrict__ psi_w0, const float* __restrict__ psi_b0,
    const float* __restrict__ psi_w1, const float* __restrict__ psi_b1,
    const float* __restrict__ psi_w2, const float* __restrict__ psi_b2,
    const float* __restrict__ rho_w0, const float* __restrict__ rho_b0,
    const float* __restrict__ rho_w1, const float* __restrict__ rho_b1,
    const float* __restrict__ rho_w2, const float* __restrict__ rho_b2,
    const float* __restrict__ tp_w0, const float* __restrict__ tp_b0,
    const float* __restrict__ tp_w1, const float* __restrict__ tp_b1,
    float* __restrict__ out, int Btot)
{
    extern __shared__ float sm[];
    const int tid = threadIdx.x;

    // ---- preload psi weights (once per block) ----
    for (int idx = tid; idx < HID * HID; idx += NTHREADS) {
        int k = idx >> 6, j = idx & 63;
        sm[OFF_PSI_W1T + (k >> 2) * 256 + j * 4 + (k & 3)] = psi_w1[idx];
    }
    for (int i = tid; i < 6 * HID; i += NTHREADS) sm[OFF_PSI_W0 + i] = psi_w0[i];
    for (int i = tid; i < 3 * HID; i += NTHREADS) sm[OFF_PHI_W0 + i] = phi_w0[i];
    for (int i = tid; i < HID * DLAT; i += NTHREADS) {
        sm[OFF_PSI_W2 + i] = psi_w2[i];
        sm[OFF_PHI_W2 + i] = phi_w2[i];
    }
    if (tid < HID) {
        sm[OFF_PSI_B0 + tid] = psi_b0[tid]; sm[OFF_PSI_B1 + tid] = psi_b1[tid];
        sm[OFF_PHI_B0 + tid] = phi_b0[tid]; sm[OFF_PHI_B1 + tid] = phi_b1[tid];
    }
    if (tid < DLAT) {
        sm[OFF_PSI_B2 + tid] = psi_b2[tid];
        sm[OFF_PHI_B2 + tid] = phi_b2[tid];
    }
    if (tid >= NPAIR) sm[OFF_GATE + tid] = 0.f;   // padded rows: gate = 0, persists

    // ---- pair indices (triu k=1 row-major) ----
    int pi = 0, pj = 0;
    {
        int p2 = tid, i2 = 0, cnt = NPART - 1;
        while (cnt > 0 && p2 >= cnt) { p2 -= cnt; i2++; cnt--; }
        pi = i2; pj = i2 + 1 + p2;
        if (pj >= NPART) pj = NPART - 1;
    }
    const bool active = (tid < NPAIR);
    const float gamma = ((pi < NPART / 2) == (pj < NPART / 2))
                        ? (1.0f / (DDIM + 1)) : (1.0f / (DDIM - 1));

    const int base = blockIdx.x * BPB;
    for (int b = base; b < base + BPB && b < Btot; ++b) {
        if (tid < NPART * DDIM) sm[OFF_X + tid] = x[(size_t)b * (NPART * DDIM) + tid];
        __syncthreads();

        float vals[14];
        #pragma unroll
        for (int v = 0; v < 14; v++) vals[v] = 0.f;

        // ================= Phase A: psi pair features + h0 (packed, transposed store) =================
        if (active) {
            float d0 = sm[OFF_X + pi * 3 + 0] - sm[OFF_X + pj * 3 + 0];
            float d1 = sm[OFF_X + pi * 3 + 1] - sm[OFF_X + pj * 3 + 1];
            float d2 = sm[OFF_X + pi * 3 + 2] - sm[OFF_X + pj * 3 + 2];
            float r2 = d0 * d0 + d1 * d1 + d2 * d2;
            float r = sqrtf(r2 + 1.1920929e-7f);
            float rt2 = r2 + 0.04f;
            float u = rt2 * 25.0f;
            float tt = __fdividef(1.0f, 1.0f + u);
            float feat[6];
            float s1v = -__logf(tt);
            feat[0] = s1v;
            feat[1] = __fdividef(r2, rt2);
            feat[2] = u * __expf(-u);
            feat[4] = tt;                        // exp(-s1) = (1+u)^-1
            float t2v = tt * tt;
            feat[5] = t2v * t2v;                 // exp(-4 s1)
            feat[3] = sqrtf(sqrtf(tt));          // exp(-0.25 s1)
            float gatev = __fdividef(r2, r2 + 0.09f);
            sm[OFF_GATE + tid] = gatev;
            vals[5] = gatev;
            vals[6] = s1v;
            vals[7] = gamma * r * __expf(-r);

            ull feat2[6];
            #pragma unroll
            for (int i = 0; i < 6; i++) feat2[i] = dup2(feat[i]);

            const ulonglong2* w0p = (const ulonglong2*)(sm + OFF_PSI_W0);
            const ulonglong2* b0p = (const ulonglong2*)(sm + OFF_PSI_B0);
            #pragma unroll 2
            for (int kt = 0; kt < 16; kt++) {
                ulonglong2 bb = b0p[kt];
                ull alo = bb.x, ahi = bb.y;
                #pragma unroll
                for (int i = 0; i < 6; i++) {
                    ulonglong2 ww = w0p[i * 16 + kt];
                    alo = fma2(feat2[i], ww.x, alo);
                    ahi = fma2(feat2[i], ww.y, ahi);
                }
                float2 g0 = unpack2(gelu2(alo));
                float2 g1 = unpack2(gelu2(ahi));
                float* dst = sm + OFF_H0S + kt * 512 + tid;
                dst[0]   = g0.x;
                dst[128] = g0.y;
                dst[256] = g1.x;
                dst[384] = g1.y;
            }
        } else {
            #pragma unroll
            for (int kt = 0; kt < 16; kt++) {
                float* dst = sm + OFF_H0S + kt * 512 + tid;
                dst[0] = 0.f; dst[128] = 0.f; dst[256] = 0.f; dst[384] = 0.f;
            }
        }
        __syncthreads();

        // ================= psi h1 GEMM, packed f32x2 (128x64 @ 64x64) =================
        {
            const int rg = tid >> 4, cg = tid & 15;
            const int r0 = rg * 16;
            ull acc[8][4];
            #pragma unroll
            for (int c = 0; c < 4; c++) {
                ull bi = dup2(sm[OFF_PSI_B1 + cg + 16 * c]);
                #pragma unroll
                for (int q = 0; q < 8; q++) acc[q][c] = bi;
            }
            const float4* w1t4 = (const float4*)(sm + OFF_PSI_W1T);
            #pragma unroll 1
            for (int kt = 0; kt < 16; kt++) {
                float4 bv0 = w1t4[kt * 64 + cg];
                float4 bv1 = w1t4[kt * 64 + cg + 16];
                float4 bv2 = w1t4[kt * 64 + cg + 32];
                float4 bv3 = w1t4[kt * 64 + cg + 48];
                const float* hbase = sm + OFF_H0S + kt * 512 + r0;
                #define KC_STEP(kc, comp)                                           \
                {                                                                   \
                    ull b20 = dup2(bv0.comp);                                       \
                    ull b21 = dup2(bv1.comp);                                       \
                    ull b22 = dup2(bv2.comp);                                       \
                    ull b23 = dup2(bv3.comp);                                       \
                    const ulonglong2* ap =                                          \
                        (const ulonglong2*)(hbase + (kc) * 128);                    \
                    _Pragma("unroll")                                               \
                    for (int q2 = 0; q2 < 4; q2++) {                                \
                        ulonglong2 aa = ap[q2];                                     \
                        ffma2(acc[2 * q2][0], aa.x, b20);                           \
                        ffma2(acc[2 * q2][1], aa.x, b21);                           \
                        ffma2(acc[2 * q2][2], aa.x, b22);                           \
                        ffma2(acc[2 * q2][3], aa.x, b23);                           \
                        ffma2(acc[2 * q2 + 1][0], aa.y, b20);                       \
                        ffma2(acc[2 * q2 + 1][1], aa.y, b21);                       \
                        ffma2(acc[2 * q2 + 1][2], aa.y, b22);                       \
                        ffma2(acc[2 * q2 + 1][3], aa.y, b23);                       \
                    }                                                               \
                }
                KC_STEP(0, x) KC_STEP(1, y) KC_STEP(2, z) KC_STEP(3, w)
                #undef KC_STEP
            }
            // epilogue: packed gelu -> gate -> W2 -> partial sums
            const ull* gt2p = (const ull*)(sm + OFF_GATE + r0);
            #pragma unroll
            for (int c = 0; c < 4; c++) {
                const int j = cg + 16 * c;
                float w2r[5];
                #pragma unroll
                for (int d = 0; d < 5; d++) w2r[d] = sm[OFF_PSI_W2 + j * 5 + d];
                #pragma unroll
                for (int q = 0; q < 8; q++) {
                    ull pr = mul2(gelu2(acc[q][c]), gt2p[q]);
                    float2 prf = unpack2(pr);
                    float g = prf.x + prf.y;
                    #pragma unroll
                    for (int d = 0; d < 5; d++) vals[d] += g * w2r[d];
                }
            }
        }
        __syncthreads();  // h0s region about to be reused by phi

        // ===== phi W1T reload (into h0s upper half) + phi h0 + time features =====
        {
            const float4* gw = (const float4*)phi_w1;
            #pragma unroll
            for (int i = 0; i < 8; i++) {
                int idx4 = tid + 128 * i;          // float4 index 0..1023
                float4 v = gw[idx4];
                int k = idx4 >> 4;
                int j0 = (idx4 & 15) * 4;
                float* d = sm + OFF_PHI_W1T + (k >> 2) * 256 + (k & 3) + j0 * 4;
                d[0] = v.x; d[4] = v.y; d[8] = v.z; d[12] = v.w;
            }
        }
        {
            int p = tid >> 3, c3 = tid & 7;
            float xv0 = sm[OFF_X + p * 3 + 0];
            float xv1 = sm[OFF_X + p * 3 + 1];
            float xv2 = sm[OFF_X + p * 3 + 2];
            const float4* w0 = (const float4*)(sm + OFF_PHI_W0);
            const float4* b0 = (const float4*)(sm + OFF_PHI_B0);
            float4* h0w = (float4*)(sm + OFF_H0S);
            #pragma unroll
            for (int t = 0; t < 2; t++) {
                int kt = 2 * c3 + t;
                float4 a = b0[kt];
                float4 w;
                w = w0[0 * 16 + kt];
                a.x += xv0 * w.x; a.y += xv0 * w.y; a.z += xv0 * w.z; a.w += xv0 * w.w;
                w = w0[1 * 16 + kt];
                a.x += xv1 * w.x; a.y += xv1 * w.y; a.z += xv1 * w.z; a.w += xv1 * w.w;
                w = w0[2 * 16 + kt];
                a.x += xv2 * w.x; a.y += xv2 * w.y; a.z += xv2 * w.z; a.w += xv2 * w.w;
                a.x = gelu_f(a.x); a.y = gelu_f(a.y);
                a.z = gelu_f(a.z); a.w = gelu_f(a.w);
                h0w[kt * 16 + p] = a;
            }
        }
        float tb = tau[b];
        if (tid == 0) sm[OFF_TF + 0] = tb;
        if (tid < NFREQ) {
            float ft = freqs[tid] * tb;
            sm[OFF_TF + 1 + tid] = __sinf(ft);
            sm[OFF_TF + 1 + NFREQ + tid] = __cosf(ft);
        }
        __syncthreads();

        // ================= Phi h1 GEMM (16x64 @ 64x64) =================
        {
            int row = tid >> 3, cg = tid & 7;
            float acc8[8];
            #pragma unroll
            for (int c = 0; c < 8; c++) acc8[c] = sm[OFF_PHI_B1 + cg + 8 * c];
            const float4* w1t = (const float4*)(sm + OFF_PHI_W1T);
            const float4* h0 = (const float4*)(sm + OFF_H0S);
            #pragma unroll 2
            for (int kt = 0; kt < 16; kt++) {
                float4 a = h0[kt * 16 + row];
                #pragma unroll
                for (int c = 0; c < 8; c++) {
                    float4 bv = w1t[kt * 64 + cg + 8 * c];
                    acc8[c] += a.x * bv.x; acc8[c] += a.y * bv.y;
                    acc8[c] += a.z * bv.z; acc8[c] += a.w * bv.w;
                }
            }
            #pragma unroll
            for (int c = 0; c < 8; c++) {
                float g = gelu_f(acc8[c]);
                #pragma unroll
                for (int d = 0; d < 5; d++)
                    vals[8 + d] += g * sm[OFF_PHI_W2 + (cg + 8 * c) * 5 + d];
            }
        }
        if (tid < NPART * DDIM) {
            float xv = sm[OFF_X + tid];
            vals[13] = xv * xv;
        }

        // ================= fused 14-value block reduction =================
        {
            const int lane = tid & 31, wid = tid >> 5;
            #pragma unroll
            for (int v = 0; v < 14; v++) {
                float t = vals[v];
                #pragma unroll
                for (int o = 16; o > 0; o >>= 1)
                    t += __shfl_down_sync(0xffffffffu, t, o);
                if (lane == 0) sm[OFF_RED + v * 4 + wid] = t;
            }
        }
        __syncthreads();
        if (tid < 14) {
            float s = sm[OFF_RED + tid * 4 + 0] + sm[OFF_RED + tid * 4 + 1]
                    + sm[OFF_RED + tid * 4 + 2] + sm[OFF_RED + tid * 4 + 3];
            if (tid < 5) {
                float gs = sm[OFF_RED + 20] + sm[OFF_RED + 21]
                         + sm[OFF_RED + 22] + sm[OFF_RED + 23];
                sm[OFF_RHOIN + 5 + tid] = (s + sm[OFF_PSI_B2 + tid] * gs) * (1.0f / NPAIR);
            } else if (tid == 6) {
                sm[OFF_RHOIN + 11] = s * (1.0f / NPAIR);
            } else if (tid == 7) {
                sm[OFF_MISC + 0] = s;   // cusp sum
            } else if (tid >= 8 && tid < 13) {
                sm[OFF_RHOIN + (tid - 8)] = s * (1.0f / NPART) + sm[OFF_PHI_B2 + tid - 8];
            } else if (tid == 13) {
                sm[OFF_RHOIN + 10] = s * (1.0f / (NPART * DDIM));
            }
        }
        // temb layer 1 (sTF synced by the reduction barrier)
        if (tid < TEMB) {
            float a = tp_b0[tid];
            #pragma unroll
            for (int i2 = 0; i2 < 2 * NFREQ + 1; i2++)
                a += sm[OFF_TF + i2] * tp_w0[i2 * TEMB + tid];
            sm[OFF_HT + tid] = gelu_f(a);
        }
        __syncthreads();
        if (tid < TEMB) {
            float a = tp_b1[tid];
            #pragma unroll
            for (int i2 = 0; i2 < TEMB; i2++)
                a += sm[OFF_HT + i2] * tp_w1[i2 * TEMB + tid];
            sm[OFF_RHOIN + 12 + tid] = a;
        }
        __syncthreads();

        // ================= rho MLP (28 -> 64 -> 64 -> 1) =================
        if (tid < HID) {
            float a = rho_b0[tid];
            #pragma unroll 4
            for (int i2 = 0; i2 < RHOIN; i2++)
                a += sm[OFF_RHOIN + i2] * rho_w0[i2 * HID + tid];
            sm[OFF_RH0 + tid] = gelu_f(a);
        }
        __syncthreads();
        float part = 0.f;
        if (tid < HID) {
            float a = rho_b1[tid];
            #pragma unroll 4
            for (int k = 0; k < HID; k++)
                a += sm[OFF_RH0 + k] * rho_w1[k * HID + tid];
            part = gelu_f(a) * rho_w2[tid];
        }
        float osum = blockReduceSum(part, sm + OFF_RED);
        if (tid == 0) out[b] = osum + rho_b2[0] + sm[OFF_MISC + 0];
        __syncthreads();
    }
}

extern "C" void kernel_launch(void* const* d_in, const int* in_sizes, int n_in,
                              void* d_out, int out_size) {
    const float* x      = (const float*)d_in[0];
    const float* tau    = (const float*)d_in[1];
    const float* freqs  = (const float*)d_in[2];
    const float* phi_w0 = (const float*)d_in[3];
    const float* phi_b0 = (const float*)d_in[4];
    const float* phi_w1 = (const float*)d_in[5];
    const float* phi_b1 = (const float*)d_in[6];
    const float* phi_w2 = (const float*)d_in[7];
    const float* phi_b2 = (const float*)d_in[8];
    const float* psi_w0 = (const float*)d_in[9];
    const float* psi_b0 = (const float*)d_in[10];
    const float* psi_w1 = (const float*)d_in[11];
    const float* psi_b1 = (const float*)d_in[12];
    const float* psi_w2 = (const float*)d_in[13];
    const float* psi_b2 = (const float*)d_in[14];
    const float* rho_w0 = (const float*)d_in[15];
    const float* rho_b0 = (const float*)d_in[16];
    const float* rho_w1 = (const float*)d_in[17];
    const float* rho_b1 = (const float*)d_in[18];
    const float* rho_w2 = (const float*)d_in[19];
    const float* rho_b2 = (const float*)d_in[20];
    const float* tp_w0  = (const float*)d_in[21];
    const float* tp_b0  = (const float*)d_in[22];
    const float* tp_w1  = (const float*)d_in[23];
    const float* tp_b1  = (const float*)d_in[24];
    float* out = (float*)d_out;

    const int Btot = in_sizes[1];
    const int nblocks = (Btot + BPB - 1) / BPB;

    cudaFuncSetAttribute(tau_jastrow_kernel,
                         cudaFuncAttributeMaxDynamicSharedMemorySize, SMEM_BYTES);

    tau_jastrow_kernel<<<nblocks, NTHREADS, SMEM_BYTES>>>(
        x, tau, freqs,
        phi_w0, phi_b0, phi_w1, phi_b1, phi_w2, phi_b2,
        psi_w0, psi_b0, psi_w1, psi_b1, psi_w2, psi_b2,
        rho_w0, rho_b0, rho_w1, rho_b1, rho_w2, rho_b2,
        tp_w0, tp_b0, tp_w1, tp_b1,
        out, Btot);
}